// round 12
// baseline (speedup 1.0000x reference)
#include <cuda_runtime.h>
#include <cuda_bf16.h>
#include <cuda_fp16.h>
#include <math.h>
#include <stdint.h>

// ---------------------------------------------------------------------------
// TensoRF_Slim: fused TensoRF feature sampling + volume rendering.
// Round 12: block-level spatial cells (16^3, Morton) + per-block SMEM staging
// of the three plane tiles (app 3x20.7KB + density 3x6.9KB = 84.7KB dyn smem).
// Corner fetches become LDS.128 instead of divergent LDG -> removes the
// structural 9.5-texel-footprint wavefront floor measured through R11.
// Alpha cheap-path (R9) and fp16 channel-last layout (R4) kept.
// ---------------------------------------------------------------------------

#define MAXG 300
#define GG (MAXG * MAXG)
#define NBINS 4096               // 16^3 cells
#define NSCANBLK 16              // NBINS / 256
#define MAXPTS (4096 * 256)
#define TILEMAX 21               // cellw(<=19) + 2

// Device-global scratch (static allocation; no runtime allocs allowed).
__device__ __align__(16) __half g_dplanesH[3 * GG * 8];    // (3, G*G, 8)
__device__ __align__(16) __half g_aplanesH[3 * GG * 24];   // (3, G*G, 24)
__device__ __align__(16) __half g_dlinesH[3 * MAXG * 8];   // (3, G, 8)
__device__ __align__(16) __half g_alinesH[3 * MAXG * 24];  // (3, G, 24)

__device__ int    g_cnt[NBINS];
__device__ int    g_off[NBINS];     // chunk-local excl offsets (mutated by scatter)
__device__ int    g_off2[NBINS];    // pristine copy for block range lookup
__device__ int    g_bsum[NSCANBLK];
__device__ int    g_bpref[NSCANBLK];
__device__ int    g_slot[MAXPTS];     // original idx -> sorted slot
__device__ float4 g_sorted[MAXPTS];   // normalized p.xyz (sorted order)
__device__ float4 g_featS[MAXPTS];    // sigma_feat, rgb0..2 (sorted order)

// ---------------------------------------------------------------------------
// Fused transpose: all four tensors (3, C, P) fp32 -> (3, P, C) fp16.
// ---------------------------------------------------------------------------
__global__ void transpose_all_kernel(const float* __restrict__ dp,
                                     const float* __restrict__ ap,
                                     const float* __restrict__ dl,
                                     const float* __restrict__ al,
                                     int G) {
    __shared__ float tile[32][25];
    int type = blockIdx.y / 3;
    int i    = blockIdx.y % 3;

    int P, C;
    const float* src;
    __half* dst;
    switch (type) {
        case 0:  P = G * G; C = 8;  src = dp; dst = g_dplanesH; break;
        case 1:  P = G * G; C = 24; src = ap; dst = g_aplanesH; break;
        case 2:  P = G;     C = 8;  src = dl; dst = g_dlinesH;  break;
        default: P = G;     C = 24; src = al; dst = g_alinesH;  break;
    }
    int p0 = blockIdx.x * 32;
    if (p0 >= P) return;

    src += (size_t)i * C * P;
    dst += (size_t)i * P * C;

    for (int j = threadIdx.x; j < C * 32; j += blockDim.x) {
        int c = j >> 5, pp = j & 31;
        int p = p0 + pp;
        tile[pp][c] = (p < P) ? src[(size_t)c * P + p] : 0.f;
    }
    __syncthreads();
    for (int j = threadIdx.x; j < C * 32; j += blockDim.x) {
        int pp = j / C, c = j - pp * C;
        int p = p0 + pp;
        if (p < P) dst[(size_t)p * C + c] = __float2half_rn(tile[pp][c]);
    }
}

// ---------------------------------------------------------------------------
// Binning: cell = i0 / cellw per axis (integer-exact, same floats everywhere),
// 4-bit Morton interleave -> 12-bit bin.
// ---------------------------------------------------------------------------
__device__ __forceinline__ uint32_t part1by2_5(uint32_t x) {
    x &= 31u;
    x = (x | (x << 8)) & 0x100Fu;
    x = (x | (x << 4)) & 0x10C3u;
    x = (x | (x << 2)) & 0x1249u;
    return x;
}

__device__ __forceinline__ int compact3_4(uint32_t m) {
    return (int)((m & 1u) | ((m >> 2) & 2u) | ((m >> 4) & 4u) | ((m >> 6) & 8u));
}

__device__ __forceinline__ void normalize_p(const float* __restrict__ xyz,
                                            const float* __restrict__ aabb,
                                            int i, float* p) {
#pragma unroll
    for (int k = 0; k < 3; k++) {
        float lo = aabb[k], hi = aabb[3 + k];
        float inv = 2.0f / (hi - lo);
        p[k] = (xyz[i * 3 + k] - lo) * inv - 1.0f;
    }
}

__device__ __forceinline__ uint32_t bin_of_p(const float* p, int G, int cellw) {
    uint32_t q[3];
#pragma unroll
    for (int k = 0; k < 3; k++) {
        float u = (p[k] + 1.0f) * 0.5f * (float)(G - 1);
        int i0 = (int)floorf(u);
        i0 = max(0, min(i0, G - 1));
        q[k] = (uint32_t)(i0 / cellw);
    }
    return part1by2_5(q[0]) | (part1by2_5(q[1]) << 1) | (part1by2_5(q[2]) << 2);
}

__global__ void hist_kernel(const float* __restrict__ xyz,
                            const float* __restrict__ aabb, int N, int G,
                            int cellw) {
    int i = blockIdx.x * blockDim.x + threadIdx.x;
    if (i >= N) return;
    float p[3];
    normalize_p(xyz, aabb, i, p);
    atomicAdd(&g_cnt[bin_of_p(p, G, cellw)], 1);
}

// ---------------------------------------------------------------------------
// Two-level scan (4096 bins).
// ---------------------------------------------------------------------------
__device__ __forceinline__ int block_excl_scan_256(int v, int t) {
    __shared__ int wsum[8];
    int lane = t & 31, w = t >> 5;
    int incl = v;
#pragma unroll
    for (int o = 1; o < 32; o <<= 1) {
        int u = __shfl_up_sync(0xFFFFFFFFu, incl, o);
        if (lane >= o) incl += u;
    }
    if (lane == 31) wsum[w] = incl;
    __syncthreads();
    if (w == 0 && lane < 8) {
        int x = wsum[lane];
        int ix = x;
#pragma unroll
        for (int o = 1; o < 8; o <<= 1) {
            int u = __shfl_up_sync(0xFFu, ix, o);
            if (lane >= o) ix += u;
        }
        wsum[lane] = ix - x;
    }
    __syncthreads();
    return incl - v + wsum[w];
}

__global__ void scanA_kernel() {
    int b = blockIdx.x, t = threadIdx.x;
    int idx = b * 256 + t;
    int v = g_cnt[idx];
    int excl = block_excl_scan_256(v, t);
    g_off[idx]  = excl;
    g_off2[idx] = excl;
    if (t == 255) g_bsum[b] = excl + v;
}

__global__ void scanB_kernel() {
    int t = threadIdx.x;   // 32 threads, first 16 active
    int v = (t < NSCANBLK) ? g_bsum[t] : 0;
    int incl = v;
#pragma unroll
    for (int o = 1; o < 32; o <<= 1) {
        int u = __shfl_up_sync(0xFFFFFFFFu, incl, o);
        if (t >= o) incl += u;
    }
    if (t < NSCANBLK) g_bpref[t] = incl - v;
}

__global__ void scatter_kernel(const float* __restrict__ xyz,
                               const float* __restrict__ aabb, int N, int G,
                               int cellw) {
    int i = blockIdx.x * blockDim.x + threadIdx.x;
    if (i >= N) return;
    float p[3];
    normalize_p(xyz, aabb, i, p);
    uint32_t b = bin_of_p(p, G, cellw);
    int slot = g_bpref[b >> 8] + atomicAdd(&g_off[b], 1);
    g_sorted[slot] = make_float4(p[0], p[1], p[2], 0.f);
    g_slot[i] = slot;
}

// ---------------------------------------------------------------------------
// fp16 vector helpers
// ---------------------------------------------------------------------------
__device__ __forceinline__ void acc8(float* acc, float w, uint4 v) {
    const __half2* h = reinterpret_cast<const __half2*>(&v);
#pragma unroll
    for (int j = 0; j < 4; j++) {
        float2 f = __half22float2(h[j]);
        acc[2 * j + 0] = fmaf(w, f.x, acc[2 * j + 0]);
        acc[2 * j + 1] = fmaf(w, f.y, acc[2 * j + 1]);
    }
}

// ---------------------------------------------------------------------------
// Feature kernel: one block per spatial cell. Stage the cell's 3 app tiles
// and 3 density tiles into dyn smem, then all corner fetches are LDS.
// ---------------------------------------------------------------------------
#define APPSTRIDE (TILEMAX * TILEMAX * 3)   // uint4 per app tile  (1323)
#define DENSTRIDE (TILEMAX * TILEMAX)       // uint4 per den tile  (441)
#define DENBASE   (3 * APPSTRIDE)
#define FEAT_SMEM ((3 * APPSTRIDE + 3 * DENSTRIDE) * 16)   // 84672 B

__global__ __launch_bounds__(256)
void feature_kernel(const float* __restrict__ wd,     // (1,24)
                    const float* __restrict__ wa,     // (3,72)
                    int N, int G, int cellw) {
    extern __shared__ __align__(16) char dynsmem[];
    uint4* sm = reinterpret_cast<uint4*>(dynsmem);

    __shared__ float s_wd[24];
    __shared__ float s_wa[216];

    const int tid = threadIdx.x;
    if (tid < 24) s_wd[tid] = wd[tid];
    for (int j = tid; j < 216; j += blockDim.x) s_wa[j] = wa[j];

    const uint32_t sb = blockIdx.x;
    const int start = g_bpref[sb >> 8] + g_off2[sb];
    const int end   = (sb == NBINS - 1) ? N : g_bpref[(sb + 1) >> 8] + g_off2[sb + 1];
    if (start >= end) return;

    const int mat_a[3] = {0, 0, 1};
    const int mat_b[3] = {1, 2, 2};
    const int vec_m[3] = {2, 1, 0};

    int cell[3] = {compact3_4(sb), compact3_4(sb >> 1), compact3_4(sb >> 2)};
    int tb[3]   = {cell[0] * cellw, cell[1] * cellw, cell[2] * cellw};
    const int tilew = cellw + 2;        // <= TILEMAX

    // ---- stage tiles ----
#pragma unroll
    for (int i = 0; i < 3; i++) {
        int a = mat_a[i], b = mat_b[i];
        const uint4* gp = reinterpret_cast<const uint4*>(g_aplanesH + (size_t)i * GG * 24);
        int tot = tilew * tilew * 3;
        for (int j = tid; j < tot; j += 256) {
            int r = j / (tilew * 3);
            int t = j - r * tilew * 3;
            int c = t / 3, q = t - c * 3;
            int y = min(tb[b] + r, G - 1);
            int x = min(tb[a] + c, G - 1);
            sm[i * APPSTRIDE + (r * TILEMAX + c) * 3 + q] = gp[(y * G + x) * 3 + q];
        }
        const uint4* gd = reinterpret_cast<const uint4*>(g_dplanesH + (size_t)i * GG * 8);
        int totd = tilew * tilew;
        for (int j = tid; j < totd; j += 256) {
            int r = j / tilew, c = j - r * tilew;
            int y = min(tb[b] + r, G - 1);
            int x = min(tb[a] + c, G - 1);
            sm[DENBASE + i * DENSTRIDE + r * TILEMAX + c] = gd[y * G + x];
        }
    }
    __syncthreads();

    // ---- point loop ----
    for (int j = start + tid; j < end; j += 256) {
        float4 sp = g_sorted[j];
        float p[3] = {sp.x, sp.y, sp.z};

        int i0[3], i1[3];
        float fr[3];
#pragma unroll
        for (int k = 0; k < 3; k++) {
            float u  = (p[k] + 1.0f) * 0.5f * (float)(G - 1);
            float uf = floorf(u);
            fr[k] = u - uf;
            int a0 = (int)uf;
            a0 = max(0, min(a0, G - 1));
            i0[k] = a0;
            i1[k] = min(a0 + 1, G - 1);
        }

        // density
        float sigma_feat = 0.0f;
#pragma unroll
        for (int i = 0; i < 3; i++) {
            int xa = mat_a[i], yb = mat_b[i], vv = vec_m[i];
            int lx0 = i0[xa] - tb[xa], lx1 = i1[xa] - tb[xa];
            int ly0 = i0[yb] - tb[yb], ly1 = i1[yb] - tb[yb];
            float wx = fr[xa], wy = fr[yb];
            float w00 = (1.f - wx) * (1.f - wy);
            float w01 = wx * (1.f - wy);
            float w10 = (1.f - wx) * wy;
            float w11 = wx * wy;

            const uint4* dt = sm + DENBASE + i * DENSTRIDE;
            float pf[8];
#pragma unroll
            for (int c = 0; c < 8; c++) pf[c] = 0.f;
            acc8(pf, w00, dt[ly0 * TILEMAX + lx0]);
            acc8(pf, w01, dt[ly0 * TILEMAX + lx1]);
            acc8(pf, w10, dt[ly1 * TILEMAX + lx0]);
            acc8(pf, w11, dt[ly1 * TILEMAX + lx1]);

            const uint4* gl = reinterpret_cast<const uint4*>(g_dlinesH + (size_t)i * MAXG * 8);
            int t0 = i0[vv], t1 = i1[vv];
            float wt = fr[vv];
            float lf[8];
#pragma unroll
            for (int c = 0; c < 8; c++) lf[c] = 0.f;
            acc8(lf, 1.f - wt, gl[t0]);
            acc8(lf, wt,       gl[t1]);

            const float* w8 = &s_wd[i * 8];
#pragma unroll
            for (int c = 0; c < 8; c++)
                sigma_feat += w8[c] * (pf[c] * lf[c]);
        }

        // appearance
        float rgb0 = 0.f, rgb1 = 0.f, rgb2 = 0.f;
#pragma unroll
        for (int i = 0; i < 3; i++) {
            int xa = mat_a[i], yb = mat_b[i], vv = vec_m[i];
            int lx0 = i0[xa] - tb[xa], lx1 = i1[xa] - tb[xa];
            int ly0 = i0[yb] - tb[yb], ly1 = i1[yb] - tb[yb];
            float wx = fr[xa], wy = fr[yb];
            float w00 = (1.f - wx) * (1.f - wy);
            float w01 = wx * (1.f - wy);
            float w10 = (1.f - wx) * wy;
            float w11 = wx * wy;

            const uint4* at = sm + i * APPSTRIDE;
            int o00 = (ly0 * TILEMAX + lx0) * 3, o01 = (ly0 * TILEMAX + lx1) * 3;
            int o10 = (ly1 * TILEMAX + lx0) * 3, o11 = (ly1 * TILEMAX + lx1) * 3;

            const uint4* gl = reinterpret_cast<const uint4*>(g_alinesH + (size_t)i * MAXG * 24);
            int t0 = i0[vv] * 3, t1 = i1[vv] * 3;
            float wt = fr[vv];

#pragma unroll
            for (int q = 0; q < 3; q++) {
                float f8[8], l8[8];
#pragma unroll
                for (int c = 0; c < 8; c++) { f8[c] = 0.f; l8[c] = 0.f; }
                acc8(f8, w00, at[o00 + q]);
                acc8(f8, w01, at[o01 + q]);
                acc8(f8, w10, at[o10 + q]);
                acc8(f8, w11, at[o11 + q]);
                acc8(l8, 1.f - wt, gl[t0 + q]);
                acc8(l8, wt,       gl[t1 + q]);

                const float* wrow = &s_wa[i * 24 + q * 8];
#pragma unroll
                for (int c = 0; c < 8; c++) {
                    float fl = f8[c] * l8[c];
                    rgb0 = fmaf(wrow[c],       fl, rgb0);
                    rgb1 = fmaf(wrow[72 + c],  fl, rgb1);
                    rgb2 = fmaf(wrow[144 + c], fl, rgb2);
                }
            }
        }

        g_featS[j] = make_float4(sigma_feat, rgb0, rgb1, rgb2);
    }
}

// ---------------------------------------------------------------------------
// Composite: per-ray. Cheap alpha path (R9): fp32 MUFU softplus for xs<<0,
// double polynomial for 1-exp(-x) at tiny x; fp64 exp fallbacks otherwise.
// ---------------------------------------------------------------------------
__global__ __launch_bounds__(256)
void composite_kernel(const float* __restrict__ z_vals,
                      float* __restrict__ out,          // (Nr,3)
                      int Ns) {
    __shared__ float s_scan[8];
    __shared__ float s_red[8 * 3];

    const int r = blockIdx.x;
    const int s = threadIdx.x;
    const int lane = s & 31;
    const int warp = s >> 5;
    const int idx = r * Ns + s;

    float4 ft = g_featS[g_slot[idx]];

    float z_s = z_vals[idx];
    float dist;
    if (s < Ns - 1) dist = z_vals[idx + 1] - z_s;
    else            dist = z_s - z_vals[idx - 1];
    float dist25 = dist * 25.0f;

    float xs = ft.x - 10.0f;
    float sig;
    if (xs < -3.0f) {
        float u = __expf(xs);
        sig = u * (1.0f - u * (0.5f - 0.33333333f * u));
    } else {
        double xd = (double)xs;
        sig = (float)(fmax(xd, 0.0) + log1p(exp(-fabs(xd))));
    }

    double x = (double)sig * (double)dist25;
    float alpha;
    if (x < 1e-3) {
        double e = 1.0 - x * (1.0 - x * (0.5 - x * (1.0 / 6.0)));
        alpha = 1.0f - (float)e;
    } else {
        alpha = 1.0f - (float)exp(-x);
    }

    float m = 1.0f - alpha + 1e-10f;
    float v = m;
#pragma unroll
    for (int o = 1; o < 32; o <<= 1) {
        float t = __shfl_up_sync(0xFFFFFFFFu, v, o);
        if (lane >= o) v *= t;
    }
    float excl = __shfl_up_sync(0xFFFFFFFFu, v, 1);
    if (lane == 0) excl = 1.0f;
    if (lane == 31) s_scan[warp] = v;
    __syncthreads();
    float pre = 1.0f;
    for (int w = 0; w < warp; w++) pre *= s_scan[w];
    float T = pre * excl;
    float wgt = alpha * T;

    float a0 = wgt * ft.y, a1 = wgt * ft.z, a2 = wgt * ft.w;
#pragma unroll
    for (int o = 16; o > 0; o >>= 1) {
        a0 += __shfl_xor_sync(0xFFFFFFFFu, a0, o);
        a1 += __shfl_xor_sync(0xFFFFFFFFu, a1, o);
        a2 += __shfl_xor_sync(0xFFFFFFFFu, a2, o);
    }
    if (lane == 0) {
        s_red[warp * 3 + 0] = a0;
        s_red[warp * 3 + 1] = a1;
        s_red[warp * 3 + 2] = a2;
    }
    __syncthreads();
    if (s == 0) {
        float o0 = 0.f, o1 = 0.f, o2 = 0.f;
        int nw = blockDim.x >> 5;
        for (int w = 0; w < nw; w++) {
            o0 += s_red[w * 3 + 0];
            o1 += s_red[w * 3 + 1];
            o2 += s_red[w * 3 + 2];
        }
        out[r * 3 + 0] = o0;
        out[r * 3 + 1] = o1;
        out[r * 3 + 2] = o2;
    }
}

// ---------------------------------------------------------------------------
// Launch
// ---------------------------------------------------------------------------
extern "C" void kernel_launch(void* const* d_in, const int* in_sizes, int n_in,
                              void* d_out, int out_size) {
    const float* xyz_sampled    = (const float*)d_in[0];
    // d_in[1] = viewdirs (unused)
    const float* z_vals         = (const float*)d_in[2];
    const float* density_planes = (const float*)d_in[3];
    const float* density_lines  = (const float*)d_in[4];
    const float* app_planes     = (const float*)d_in[5];
    const float* app_lines      = (const float*)d_in[6];
    const float* density_bw     = (const float*)d_in[7];
    const float* app_bw         = (const float*)d_in[8];
    const float* aabb           = (const float*)d_in[9];
    float* out = (float*)d_out;

    int Nr = in_sizes[1] / 3;
    int Ns = in_sizes[2] / Nr;
    int N  = Nr * Ns;
    int g2 = in_sizes[3] / (3 * 8);
    int G  = (int)(sqrtf((float)g2) + 0.5f);
    int cellw = (G + 15) >> 4;

    void* cnt_ptr;
    cudaGetSymbolAddress(&cnt_ptr, g_cnt);

    int P = G * G;
    {
        dim3 grid((P + 31) / 32, 12);
        transpose_all_kernel<<<grid, 256>>>(density_planes, app_planes,
                                            density_lines, app_lines, G);
    }
    cudaMemsetAsync(cnt_ptr, 0, NBINS * sizeof(int));
    hist_kernel<<<(N + 255) / 256, 256>>>(xyz_sampled, aabb, N, G, cellw);
    scanA_kernel<<<NSCANBLK, 256>>>();
    scanB_kernel<<<1, 32>>>();
    scatter_kernel<<<(N + 255) / 256, 256>>>(xyz_sampled, aabb, N, G, cellw);

    cudaFuncSetAttribute(feature_kernel,
                         cudaFuncAttributeMaxDynamicSharedMemorySize, FEAT_SMEM);
    feature_kernel<<<NBINS, 256, FEAT_SMEM>>>(density_bw, app_bw, N, G, cellw);

    composite_kernel<<<Nr, Ns>>>(z_vals, out, Ns);
}

// round 13
// speedup vs baseline: 2.0084x; 2.0084x over previous
#include <cuda_runtime.h>
#include <cuda_bf16.h>
#include <cuda_fp16.h>
#include <math.h>
#include <stdint.h>

// ---------------------------------------------------------------------------
// TensoRF_Slim: fused TensoRF feature sampling + volume rendering.
// Round 13: R11 pipeline (Morton sort + two-phase + cheap alpha) with the
// feature math rewritten in packed half2 (HFMA2): bilinear + line lerps done
// in half2 with NO per-load converts; only the 12 final 8-channel products
// are converted to fp32 for the basis dots. ~1300 -> ~670 issue-ops/point
// on a kernel shown to be convert/FMA issue-bound. R12 smem staging reverted
// (falsified twice).
// ---------------------------------------------------------------------------

#define MAXG 300
#define GG (MAXG * MAXG)
#define NBINS 32768              // 32^3
#define NSCANBLK 128             // NBINS / 256
#define MAXPTS (4096 * 256)

// Device-global scratch (static allocation; no runtime allocs allowed).
__device__ __align__(16) __half g_dplanesH[3 * GG * 8];    // (3, G*G, 8)
__device__ __align__(16) __half g_aplanesH[3 * GG * 24];   // (3, G*G, 24)
__device__ __align__(16) __half g_dlinesH[3 * MAXG * 8];   // (3, G, 8)
__device__ __align__(16) __half g_alinesH[3 * MAXG * 24];  // (3, G, 24)

__device__ int    g_cnt[NBINS];
__device__ int    g_off[NBINS];     // local (per-chunk) exclusive offsets
__device__ int    g_bsum[NSCANBLK];
__device__ int    g_bpref[NSCANBLK];
__device__ float4 g_sorted[MAXPTS];   // normalized p.xyz + orig idx
__device__ float4 g_feat[MAXPTS];     // sigma_feat, rgb0, rgb1, rgb2

// ---------------------------------------------------------------------------
// Fused transpose: all four tensors (3, C, P) fp32 -> (3, P, C) fp16.
// ---------------------------------------------------------------------------
__global__ void transpose_all_kernel(const float* __restrict__ dp,
                                     const float* __restrict__ ap,
                                     const float* __restrict__ dl,
                                     const float* __restrict__ al,
                                     int G) {
    __shared__ float tile[32][25];
    int type = blockIdx.y / 3;
    int i    = blockIdx.y % 3;

    int P, C;
    const float* src;
    __half* dst;
    switch (type) {
        case 0:  P = G * G; C = 8;  src = dp; dst = g_dplanesH; break;
        case 1:  P = G * G; C = 24; src = ap; dst = g_aplanesH; break;
        case 2:  P = G;     C = 8;  src = dl; dst = g_dlinesH;  break;
        default: P = G;     C = 24; src = al; dst = g_alinesH;  break;
    }
    int p0 = blockIdx.x * 32;
    if (p0 >= P) return;

    src += (size_t)i * C * P;
    dst += (size_t)i * P * C;

    for (int j = threadIdx.x; j < C * 32; j += blockDim.x) {
        int c = j >> 5, pp = j & 31;
        int p = p0 + pp;
        tile[pp][c] = (p < P) ? src[(size_t)c * P + p] : 0.f;
    }
    __syncthreads();
    for (int j = threadIdx.x; j < C * 32; j += blockDim.x) {
        int pp = j / C, c = j - pp * C;
        int p = p0 + pp;
        if (p < P) dst[(size_t)p * C + c] = __float2half_rn(tile[pp][c]);
    }
}

// ---------------------------------------------------------------------------
// Binning: 5-bit Morton per axis -> 15-bit bin.
// ---------------------------------------------------------------------------
__device__ __forceinline__ uint32_t part1by2_5(uint32_t x) {
    x &= 31u;
    x = (x | (x << 8)) & 0x100Fu;
    x = (x | (x << 4)) & 0x10C3u;
    x = (x | (x << 2)) & 0x1249u;
    return x;
}

__device__ __forceinline__ void normalize_p(const float* __restrict__ xyz,
                                            const float* __restrict__ aabb,
                                            int i, float* p) {
#pragma unroll
    for (int k = 0; k < 3; k++) {
        float lo = aabb[k], hi = aabb[3 + k];
        float inv = 2.0f / (hi - lo);
        p[k] = (xyz[i * 3 + k] - lo) * inv - 1.0f;
    }
}

__device__ __forceinline__ uint32_t bin_of(const float* p) {
    uint32_t q[3];
#pragma unroll
    for (int k = 0; k < 3; k++) {
        int v = (int)((p[k] + 1.0f) * 16.0f);
        q[k] = (uint32_t)max(0, min(v, 31));
    }
    return part1by2_5(q[0]) | (part1by2_5(q[1]) << 1) | (part1by2_5(q[2]) << 2);
}

__global__ void hist_kernel(const float* __restrict__ xyz,
                            const float* __restrict__ aabb, int N) {
    int i = blockIdx.x * blockDim.x + threadIdx.x;
    if (i >= N) return;
    float p[3];
    normalize_p(xyz, aabb, i, p);
    atomicAdd(&g_cnt[bin_of(p)], 1);
}

// ---------------------------------------------------------------------------
// Two-level scan.
// ---------------------------------------------------------------------------
__device__ __forceinline__ int block_excl_scan_256(int v, int t) {
    __shared__ int wsum[8];
    int lane = t & 31, w = t >> 5;
    int incl = v;
#pragma unroll
    for (int o = 1; o < 32; o <<= 1) {
        int u = __shfl_up_sync(0xFFFFFFFFu, incl, o);
        if (lane >= o) incl += u;
    }
    if (lane == 31) wsum[w] = incl;
    __syncthreads();
    if (w == 0 && lane < 8) {
        int x = wsum[lane];
        int ix = x;
#pragma unroll
        for (int o = 1; o < 8; o <<= 1) {
            int u = __shfl_up_sync(0xFFu, ix, o);
            if (lane >= o) ix += u;
        }
        wsum[lane] = ix - x;
    }
    __syncthreads();
    return incl - v + wsum[w];
}

__global__ void scanA_kernel() {
    int b = blockIdx.x, t = threadIdx.x;
    int idx = b * 256 + t;
    int v = g_cnt[idx];
    int excl = block_excl_scan_256(v, t);
    g_off[idx] = excl;
    if (t == 255) g_bsum[b] = excl + v;
}

__global__ void scanB_kernel() {
    int t = threadIdx.x;   // 128 threads
    int lane = t & 31, w = t >> 5;
    __shared__ int wsum[4];
    int v = g_bsum[t];
    int incl = v;
#pragma unroll
    for (int o = 1; o < 32; o <<= 1) {
        int u = __shfl_up_sync(0xFFFFFFFFu, incl, o);
        if (lane >= o) incl += u;
    }
    if (lane == 31) wsum[w] = incl;
    __syncthreads();
    if (t == 0) {
        int run = 0;
        for (int k = 0; k < 4; k++) { int x = wsum[k]; wsum[k] = run; run += x; }
    }
    __syncthreads();
    g_bpref[t] = incl - v + wsum[w];
}

__global__ void scatter_kernel(const float* __restrict__ xyz,
                               const float* __restrict__ aabb, int N) {
    int i = blockIdx.x * blockDim.x + threadIdx.x;
    if (i >= N) return;
    float p[3];
    normalize_p(xyz, aabb, i, p);
    uint32_t b = bin_of(p);
    int slot = g_bpref[b >> 8] + atomicAdd(&g_off[b], 1);
    g_sorted[slot] = make_float4(p[0], p[1], p[2], __int_as_float(i));
}

// ---------------------------------------------------------------------------
// half2 vector helpers: accumulate w * (4 half2 in a uint4) into acc[4].
// Pure HFMA2, no converts.
// ---------------------------------------------------------------------------
__device__ __forceinline__ void acc4h(__half2* acc, __half2 w, uint4 v) {
    const __half2* h = reinterpret_cast<const __half2*>(&v);
#pragma unroll
    for (int j = 0; j < 4; j++) acc[j] = __hfma2(w, h[j], acc[j]);
}

// ---------------------------------------------------------------------------
// Phase A: per sorted point, compute sigma_feat + rgb, scatter to g_feat.
// Bilinear + line lerps in half2; products converted once to fp32 for dots.
// ---------------------------------------------------------------------------
__global__ __launch_bounds__(256)
void feature_kernel(const float* __restrict__ wd,     // (1,24)
                    const float* __restrict__ wa,     // (3,72)
                    int N, int G) {
    __shared__ float s_wd[24];
    __shared__ float s_wa[216];

    int gid = blockIdx.x * blockDim.x + threadIdx.x;
    int s = threadIdx.x;
    if (s < 24) s_wd[s] = wd[s];
    for (int j = s; j < 216; j += blockDim.x) s_wa[j] = wa[j];
    __syncthreads();
    if (gid >= N) return;

    float4 sp = g_sorted[gid];
    float p[3] = {sp.x, sp.y, sp.z};
    int oidx = __float_as_int(sp.w);

    int i0[3], i1[3];
    float fr[3];
#pragma unroll
    for (int k = 0; k < 3; k++) {
        float u  = (p[k] + 1.0f) * 0.5f * (float)(G - 1);
        float uf = floorf(u);
        fr[k] = u - uf;
        int a0 = (int)uf;
        a0 = max(0, min(a0, G - 1));
        i0[k] = a0;
        i1[k] = min(a0 + 1, G - 1);
    }

    const int mat_a[3] = {0, 0, 1};
    const int mat_b[3] = {1, 2, 2};
    const int vec_m[3] = {2, 1, 0};

    const __half2 hz = __float2half2_rn(0.0f);

    // ---------------- density ----------------
    float sigma_feat = 0.0f;
#pragma unroll
    for (int i = 0; i < 3; i++) {
        int xa = mat_a[i], yb = mat_b[i], vv = vec_m[i];
        int x0 = i0[xa], x1 = i1[xa], y0 = i0[yb], y1 = i1[yb];
        float wx = fr[xa], wy = fr[yb];
        __half2 hw00 = __float2half2_rn((1.f - wx) * (1.f - wy));
        __half2 hw01 = __float2half2_rn(wx * (1.f - wy));
        __half2 hw10 = __float2half2_rn((1.f - wx) * wy);
        __half2 hw11 = __float2half2_rn(wx * wy);

        const uint4* gp = reinterpret_cast<const uint4*>(g_dplanesH + (size_t)i * GG * 8);
        __half2 pf2[4] = {hz, hz, hz, hz};
        acc4h(pf2, hw00, gp[y0 * G + x0]);
        acc4h(pf2, hw01, gp[y0 * G + x1]);
        acc4h(pf2, hw10, gp[y1 * G + x0]);
        acc4h(pf2, hw11, gp[y1 * G + x1]);

        const uint4* gl = reinterpret_cast<const uint4*>(g_dlinesH + (size_t)i * MAXG * 8);
        int t0 = i0[vv], t1 = i1[vv];
        float wt = fr[vv];
        __half2 hwt0 = __float2half2_rn(1.f - wt);
        __half2 hwt1 = __float2half2_rn(wt);
        __half2 lf2[4] = {hz, hz, hz, hz};
        acc4h(lf2, hwt0, gl[t0]);
        acc4h(lf2, hwt1, gl[t1]);

        const float* w8 = &s_wd[i * 8];
#pragma unroll
        for (int j = 0; j < 4; j++) {
            float2 f = __half22float2(__hmul2(pf2[j], lf2[j]));
            sigma_feat = fmaf(w8[2 * j + 0], f.x, sigma_feat);
            sigma_feat = fmaf(w8[2 * j + 1], f.y, sigma_feat);
        }
    }

    // ---------------- appearance (rgb), 8-channel chunks ----------------
    float rgb0 = 0.f, rgb1 = 0.f, rgb2 = 0.f;
#pragma unroll
    for (int i = 0; i < 3; i++) {
        int xa = mat_a[i], yb = mat_b[i], vv = vec_m[i];
        int x0 = i0[xa], x1 = i1[xa], y0 = i0[yb], y1 = i1[yb];
        float wx = fr[xa], wy = fr[yb];
        __half2 hw00 = __float2half2_rn((1.f - wx) * (1.f - wy));
        __half2 hw01 = __float2half2_rn(wx * (1.f - wy));
        __half2 hw10 = __float2half2_rn((1.f - wx) * wy);
        __half2 hw11 = __float2half2_rn(wx * wy);

        const uint4* gp = reinterpret_cast<const uint4*>(g_aplanesH + (size_t)i * GG * 24);
        int o00 = (y0 * G + x0) * 3, o01 = (y0 * G + x1) * 3;
        int o10 = (y1 * G + x0) * 3, o11 = (y1 * G + x1) * 3;

        const uint4* gl = reinterpret_cast<const uint4*>(g_alinesH + (size_t)i * MAXG * 24);
        int t0 = i0[vv] * 3, t1 = i1[vv] * 3;
        float wt = fr[vv];
        __half2 hwt0 = __float2half2_rn(1.f - wt);
        __half2 hwt1 = __float2half2_rn(wt);

#pragma unroll
        for (int q = 0; q < 3; q++) {
            __half2 f2[4] = {hz, hz, hz, hz};
            acc4h(f2, hw00, gp[o00 + q]);
            acc4h(f2, hw01, gp[o01 + q]);
            acc4h(f2, hw10, gp[o10 + q]);
            acc4h(f2, hw11, gp[o11 + q]);
            __half2 l2[4] = {hz, hz, hz, hz};
            acc4h(l2, hwt0, gl[t0 + q]);
            acc4h(l2, hwt1, gl[t1 + q]);

            const float* wrow = &s_wa[i * 24 + q * 8];
#pragma unroll
            for (int j = 0; j < 4; j++) {
                float2 f = __half22float2(__hmul2(f2[j], l2[j]));
                rgb0 = fmaf(wrow[2 * j + 0],       f.x, rgb0);
                rgb0 = fmaf(wrow[2 * j + 1],       f.y, rgb0);
                rgb1 = fmaf(wrow[72 + 2 * j + 0],  f.x, rgb1);
                rgb1 = fmaf(wrow[72 + 2 * j + 1],  f.y, rgb1);
                rgb2 = fmaf(wrow[144 + 2 * j + 0], f.x, rgb2);
                rgb2 = fmaf(wrow[144 + 2 * j + 1], f.y, rgb2);
            }
        }
    }

    g_feat[oidx] = make_float4(sigma_feat, rgb0, rgb1, rgb2);
}

// ---------------------------------------------------------------------------
// Phase B: per-ray alpha compositing (R9 cheap-alpha path, protected).
// ---------------------------------------------------------------------------
__global__ __launch_bounds__(256)
void composite_kernel(const float* __restrict__ z_vals,
                      float* __restrict__ out,          // (Nr,3)
                      int Ns) {
    __shared__ float s_scan[8];
    __shared__ float s_red[8 * 3];

    const int r = blockIdx.x;
    const int s = threadIdx.x;
    const int lane = s & 31;
    const int warp = s >> 5;
    const int idx = r * Ns + s;

    float4 ft = g_feat[idx];

    float z_s = z_vals[idx];
    float dist;
    if (s < Ns - 1) dist = z_vals[idx + 1] - z_s;
    else            dist = z_s - z_vals[idx - 1];
    float dist25 = dist * 25.0f;

    float xs = ft.x - 10.0f;
    float sig;
    if (xs < -3.0f) {
        float u = __expf(xs);
        sig = u * (1.0f - u * (0.5f - 0.33333333f * u));
    } else {
        double xd = (double)xs;
        sig = (float)(fmax(xd, 0.0) + log1p(exp(-fabs(xd))));
    }

    double x = (double)sig * (double)dist25;
    float alpha;
    if (x < 1e-3) {
        double e = 1.0 - x * (1.0 - x * (0.5 - x * (1.0 / 6.0)));
        alpha = 1.0f - (float)e;
    } else {
        alpha = 1.0f - (float)exp(-x);
    }

    float m = 1.0f - alpha + 1e-10f;
    float v = m;
#pragma unroll
    for (int o = 1; o < 32; o <<= 1) {
        float t = __shfl_up_sync(0xFFFFFFFFu, v, o);
        if (lane >= o) v *= t;
    }
    float excl = __shfl_up_sync(0xFFFFFFFFu, v, 1);
    if (lane == 0) excl = 1.0f;
    if (lane == 31) s_scan[warp] = v;
    __syncthreads();
    float pre = 1.0f;
    for (int w = 0; w < warp; w++) pre *= s_scan[w];
    float T = pre * excl;
    float wgt = alpha * T;

    float a0 = wgt * ft.y, a1 = wgt * ft.z, a2 = wgt * ft.w;
#pragma unroll
    for (int o = 16; o > 0; o >>= 1) {
        a0 += __shfl_xor_sync(0xFFFFFFFFu, a0, o);
        a1 += __shfl_xor_sync(0xFFFFFFFFu, a1, o);
        a2 += __shfl_xor_sync(0xFFFFFFFFu, a2, o);
    }
    if (lane == 0) {
        s_red[warp * 3 + 0] = a0;
        s_red[warp * 3 + 1] = a1;
        s_red[warp * 3 + 2] = a2;
    }
    __syncthreads();
    if (s == 0) {
        float o0 = 0.f, o1 = 0.f, o2 = 0.f;
        int nw = blockDim.x >> 5;
        for (int w = 0; w < nw; w++) {
            o0 += s_red[w * 3 + 0];
            o1 += s_red[w * 3 + 1];
            o2 += s_red[w * 3 + 2];
        }
        out[r * 3 + 0] = o0;
        out[r * 3 + 1] = o1;
        out[r * 3 + 2] = o2;
    }
}

// ---------------------------------------------------------------------------
// Launch
// ---------------------------------------------------------------------------
extern "C" void kernel_launch(void* const* d_in, const int* in_sizes, int n_in,
                              void* d_out, int out_size) {
    const float* xyz_sampled    = (const float*)d_in[0];
    // d_in[1] = viewdirs (unused)
    const float* z_vals         = (const float*)d_in[2];
    const float* density_planes = (const float*)d_in[3];
    const float* density_lines  = (const float*)d_in[4];
    const float* app_planes     = (const float*)d_in[5];
    const float* app_lines      = (const float*)d_in[6];
    const float* density_bw     = (const float*)d_in[7];
    const float* app_bw         = (const float*)d_in[8];
    const float* aabb           = (const float*)d_in[9];
    float* out = (float*)d_out;

    int Nr = in_sizes[1] / 3;
    int Ns = in_sizes[2] / Nr;
    int N  = Nr * Ns;
    int g2 = in_sizes[3] / (3 * 8);
    int G  = (int)(sqrtf((float)g2) + 0.5f);

    void* cnt_ptr;
    cudaGetSymbolAddress(&cnt_ptr, g_cnt);

    int P = G * G;
    {
        dim3 grid((P + 31) / 32, 12);
        transpose_all_kernel<<<grid, 256>>>(density_planes, app_planes,
                                            density_lines, app_lines, G);
    }
    cudaMemsetAsync(cnt_ptr, 0, NBINS * sizeof(int));
    hist_kernel<<<(N + 255) / 256, 256>>>(xyz_sampled, aabb, N);
    scanA_kernel<<<NSCANBLK, 256>>>();
    scanB_kernel<<<1, 128>>>();
    scatter_kernel<<<(N + 255) / 256, 256>>>(xyz_sampled, aabb, N);
    feature_kernel<<<(N + 255) / 256, 256>>>(density_bw, app_bw, N, G);
    composite_kernel<<<Nr, Ns>>>(z_vals, out, Ns);
}